// round 1
// baseline (speedup 1.0000x reference)
#include <cuda_runtime.h>

#define LS 4104           // padded time stride for activation buffers
#define NB 32
#define NT 4096
#define ND 256
#define NK 1024

// ---------------- scratch (static device globals; no allocation) ----------------
__device__ float  g_bufA[(size_t)NB * ND * LS];   // odd-layer outputs (len 4097)
__device__ float  g_bufB[(size_t)NB * ND * LS];   // even-layer outputs (len 4096)
__device__ double g_sum[ND];
__device__ double g_sumsq[ND];
__device__ float  g_scale[ND];
__device__ float  g_shift[ND];
__device__ float  g_cnorm[NK];
__device__ float  g_cnt[NK];
__device__ float  g_sumcur[(size_t)NK * ND];
__device__ float  g_n;

// ---------------- layer 1: conv 12 -> 256, k=4, pad=2, Lin=4096, Lout=4097 ------
__global__ __launch_bounds__(256) void conv1_kernel(
    const float* __restrict__ x, const float* __restrict__ w,
    const float* __restrict__ bias, float* __restrict__ out)
{
    __shared__ float in_s[12][68];
    __shared__ float w_s[64][49];
    __shared__ float o_s[64][65];
    __shared__ double ssum[64], ssq[64];

    const int tid = threadIdx.x;
    const int b = blockIdx.z, oc0 = blockIdx.y * 64, t0 = blockIdx.x * 64;
    const int ocl = tid & 63, tg = tid >> 6, tbase = tg * 16;
    const int Lout = 4097;

    for (int idx = tid; idx < 12 * 67; idx += 256) {
        int j = idx / 12, c = idx - j * 12;
        int ip = t0 - 2 + j;
        in_s[c][j] = ((unsigned)ip < 4096u) ? x[((size_t)b * NT + ip) * 12 + c] : 0.f;
    }
    for (int idx = tid; idx < 64 * 48; idx += 256) {
        int oc = idx / 48, r = idx - oc * 48;
        w_s[oc][r] = w[(size_t)(oc0 + oc) * 48 + r];
    }
    __syncthreads();

    float acc[16];
#pragma unroll
    for (int u = 0; u < 16; u++) acc[u] = 0.f;

#pragma unroll
    for (int c = 0; c < 12; c++) {
        float v[19];
#pragma unroll
        for (int u = 0; u < 19; u++) v[u] = in_s[c][tbase + u];
        float w0 = w_s[ocl][c * 4 + 0], w1 = w_s[ocl][c * 4 + 1];
        float w2 = w_s[ocl][c * 4 + 2], w3 = w_s[ocl][c * 4 + 3];
#pragma unroll
        for (int u = 0; u < 16; u++)
            acc[u] = fmaf(w3, v[u + 3], fmaf(w2, v[u + 2], fmaf(w1, v[u + 1], fmaf(w0, v[u], acc[u]))));
    }

    const float bv = bias[oc0 + ocl];
#pragma unroll
    for (int u = 0; u < 16; u++) acc[u] += bv;

    // per-channel stats (for BN of this layer's output)
    {
        double s = 0.0, q = 0.0;
#pragma unroll
        for (int u = 0; u < 16; u++)
            if (t0 + tbase + u < Lout) { double a = (double)acc[u]; s += a; q += a * a; }
        __syncthreads();
        if (tid < 64) { ssum[tid] = 0.0; ssq[tid] = 0.0; }
        __syncthreads();
        atomicAdd(&ssum[ocl], s);
        atomicAdd(&ssq[ocl], q);
        __syncthreads();
        if (tid < 64) {
            atomicAdd(&g_sum[oc0 + tid], ssum[tid]);
            atomicAdd(&g_sumsq[oc0 + tid], ssq[tid]);
        }
    }

    // coalesced store via smem transpose
    __syncthreads();
#pragma unroll
    for (int u = 0; u < 16; u++) o_s[ocl][tbase + u] = acc[u];
    __syncthreads();
    float* ob = out + ((size_t)b * ND + oc0) * LS + t0;
    for (int idx = tid; idx < 4096; idx += 256) {
        int oc = idx >> 6, t = idx & 63;
        if (t0 + t < Lout) ob[(size_t)oc * LS + t] = o_s[oc][t];
    }
}

// ---------------- generic D->D conv, BN+ReLU applied to INPUT on the fly --------
// mode 0: write [b][c][t] (stride LS); mode 1: write z_e [b][t][d] into d_out
__global__ __launch_bounds__(256) void convDD_kernel(
    const float* __restrict__ in, const float* __restrict__ w,
    const float* __restrict__ bias, float* __restrict__ out,
    int Lin, int Lout, int pad, int mode, int do_stats)
{
    __shared__ float in_s[8][68];
    __shared__ float w_s[64][33];
    __shared__ float o_s[64][65];
    __shared__ double ssum[64], ssq[64];

    const int tid = threadIdx.x;
    const int b = blockIdx.z, oc0 = blockIdx.y * 64, t0 = blockIdx.x * 64;
    const int ocl = tid & 63, tg = tid >> 6, tbase = tg * 16;

    float acc[16];
#pragma unroll
    for (int u = 0; u < 16; u++) acc[u] = 0.f;

    const float* inb = in + (size_t)b * ND * LS;
    const int base = t0 - pad;

    for (int cc = 0; cc < 256; cc += 8) {
        __syncthreads();
        for (int idx = tid; idx < 8 * 67; idx += 256) {
            int c = idx / 67, j = idx - c * 67;
            int ip = base + j;
            float v = 0.f;
            if ((unsigned)ip < (unsigned)Lin) {
                float raw = inb[(size_t)(cc + c) * LS + ip];
                v = fmaxf(fmaf(raw, g_scale[cc + c], g_shift[cc + c]), 0.f);
            }
            in_s[c][j] = v;
        }
        {
            const float* wp = w + ((size_t)oc0 * 256 + cc) * 4;
            for (int idx = tid; idx < 2048; idx += 256) {
                int oc = idx >> 5, r = idx & 31;
                w_s[oc][r] = wp[(size_t)oc * 1024 + r];
            }
        }
        __syncthreads();
#pragma unroll
        for (int c = 0; c < 8; c++) {
            float v[19];
#pragma unroll
            for (int u = 0; u < 19; u++) v[u] = in_s[c][tbase + u];
            float w0 = w_s[ocl][c * 4 + 0], w1 = w_s[ocl][c * 4 + 1];
            float w2 = w_s[ocl][c * 4 + 2], w3 = w_s[ocl][c * 4 + 3];
#pragma unroll
            for (int u = 0; u < 16; u++)
                acc[u] = fmaf(w3, v[u + 3], fmaf(w2, v[u + 2], fmaf(w1, v[u + 1], fmaf(w0, v[u], acc[u]))));
        }
    }

    const float bv = bias[oc0 + ocl];
#pragma unroll
    for (int u = 0; u < 16; u++) acc[u] += bv;

    if (do_stats) {
        double s = 0.0, q = 0.0;
#pragma unroll
        for (int u = 0; u < 16; u++)
            if (t0 + tbase + u < Lout) { double a = (double)acc[u]; s += a; q += a * a; }
        __syncthreads();
        if (tid < 64) { ssum[tid] = 0.0; ssq[tid] = 0.0; }
        __syncthreads();
        atomicAdd(&ssum[ocl], s);
        atomicAdd(&ssq[ocl], q);
        __syncthreads();
        if (tid < 64) {
            atomicAdd(&g_sum[oc0 + tid], ssum[tid]);
            atomicAdd(&g_sumsq[oc0 + tid], ssq[tid]);
        }
    }

    if (mode == 0) {
        __syncthreads();
#pragma unroll
        for (int u = 0; u < 16; u++) o_s[ocl][tbase + u] = acc[u];
        __syncthreads();
        float* ob = out + ((size_t)b * ND + oc0) * LS + t0;
        for (int idx = tid; idx < 4096; idx += 256) {
            int oc = idx >> 6, t = idx & 63;
            if (t0 + t < Lout) ob[(size_t)oc * LS + t] = o_s[oc][t];
        }
    } else {
        // z_e layout [b][t][d]: consecutive ocl -> consecutive addresses (coalesced)
        float* ob = out + (size_t)b * NT * ND + (oc0 + ocl);
#pragma unroll
        for (int u = 0; u < 16; u++) {
            int t = t0 + tbase + u;
            if (t < Lout) ob[(size_t)t * ND] = acc[u];
        }
    }
}

// ---------------- BN stats -> scale/shift for next layer; resets stats ----------
__global__ void scaleshift_kernel(const float* __restrict__ g, const float* __restrict__ be, double N)
{
    int c = threadIdx.x;
    double m = g_sum[c] / N;
    double var = g_sumsq[c] / N - m * m;
    double r = 1.0 / sqrt(var + 1e-5);
    double sc = (double)g[c] * r;
    g_scale[c] = (float)sc;
    g_shift[c] = (float)((double)be[c] - m * sc);
    g_sum[c] = 0.0;
    g_sumsq[c] = 0.0;
}

// ---------------- ||codebook_k||^2 ----------------------------------------------
__global__ void cnorm_kernel(const float* __restrict__ cb)
{
    int gw = (blockIdx.x * 256 + threadIdx.x) >> 5;
    int lane = threadIdx.x & 31;
    float s = 0.f;
    const float* row = cb + (size_t)gw * ND;
    for (int d = lane; d < ND; d += 32) { float v = row[d]; s = fmaf(v, v, s); }
#pragma unroll
    for (int off = 16; off; off >>= 1) s += __shfl_xor_sync(0xffffffffu, s, off);
    if (lane == 0) g_cnorm[gw] = s;
}

// ---------------- VQ: argmin + z_q write + counts + segment sums ----------------
// block: 64 tokens; thread = (tokg=tid>>4 -> 4 tokens, codeg=tid&15 -> 8 codes/tile)
__global__ __launch_bounds__(256) void vq_kernel(
    const float* __restrict__ ze, const float* __restrict__ cb, float* __restrict__ zq)
{
    __shared__ float z_s[64][17];
    __shared__ float c_s[128][17];
    __shared__ int sbest[64];

    const int tid = threadIdx.x;
    const int tok0 = blockIdx.x * 64;
    const int tokg = tid >> 4;
    const int codeg = tid & 15;

    float bval[4];
    int bidx[4];
#pragma unroll
    for (int i = 0; i < 4; i++) { bval[i] = 1e30f; bidx[i] = 0x7fffffff; }

    for (int ct = 0; ct < NK; ct += 128) {
        float acc[4][8];
#pragma unroll
        for (int i = 0; i < 4; i++)
#pragma unroll
            for (int j = 0; j < 8; j++) acc[i][j] = 0.f;

        for (int d0 = 0; d0 < ND; d0 += 16) {
            __syncthreads();
            for (int idx = tid; idx < 1024; idx += 256) {
                int r = idx >> 4, dj = idx & 15;
                z_s[r][dj] = ze[(size_t)(tok0 + r) * ND + d0 + dj];
            }
            for (int idx = tid; idx < 2048; idx += 256) {
                int r = idx >> 4, dj = idx & 15;
                c_s[r][dj] = cb[(size_t)(ct + r) * ND + d0 + dj];
            }
            __syncthreads();
#pragma unroll
            for (int dj = 0; dj < 16; dj++) {
                float zr[4], cr[8];
#pragma unroll
                for (int i = 0; i < 4; i++) zr[i] = z_s[tokg * 4 + i][dj];
#pragma unroll
                for (int j = 0; j < 8; j++) cr[j] = c_s[codeg + 16 * j][dj];
#pragma unroll
                for (int i = 0; i < 4; i++)
#pragma unroll
                    for (int j = 0; j < 8; j++)
                        acc[i][j] = fmaf(zr[i], cr[j], acc[i][j]);
            }
        }
#pragma unroll
        for (int j = 0; j < 8; j++) {
            int code = ct + codeg + 16 * j;
            float cn = g_cnorm[code];
#pragma unroll
            for (int i = 0; i < 4; i++) {
                float s = fmaf(-2.f, acc[i][j], cn);
                if (s < bval[i] || (s == bval[i] && code < bidx[i])) { bval[i] = s; bidx[i] = code; }
            }
        }
    }
    // reduce across the 16 code-lanes sharing each token (tie -> smaller index)
#pragma unroll
    for (int off = 8; off >= 1; off >>= 1) {
#pragma unroll
        for (int i = 0; i < 4; i++) {
            float ov = __shfl_xor_sync(0xffffffffu, bval[i], off);
            int oi = __shfl_xor_sync(0xffffffffu, bidx[i], off);
            if (ov < bval[i] || (ov == bval[i] && oi < bidx[i])) { bval[i] = ov; bidx[i] = oi; }
        }
    }
    if (codeg == 0) {
#pragma unroll
        for (int i = 0; i < 4; i++) sbest[tokg * 4 + i] = bidx[i];
    }
    __syncthreads();
    if (tid < 64) atomicAdd(&g_cnt[sbest[tid]], 1.0f);
    for (int e = tid; e < 64 * ND; e += 256) {
        int r = e >> 8, d = e & 255;
        int code = sbest[r];
        size_t gz = (size_t)(tok0 + r) * ND + d;
        float zev = ze[gz];
        float cbv = cb[(size_t)code * ND + d];
        zq[gz] = zev + (cbv - zev);   // matches z_e + (z_q - z_e) bit pattern
        atomicAdd(&g_sumcur[(size_t)code * ND + d], zev);
    }
}

// ---------------- EMA epilogue ---------------------------------------------------
__global__ void ema1_kernel(const float* __restrict__ ecs, float* __restrict__ necs)
{
    __shared__ float red[1024];
    int k = threadIdx.x;
    float ne = ecs[k] * 0.99f + 0.01f * g_cnt[k];
    necs[k] = ne;
    g_cnt[k] = 0.f;        // self-reset for next graph replay
    red[k] = ne;
    __syncthreads();
    for (int off = 512; off; off >>= 1) {
        if (k < off) red[k] += red[k + off];
        __syncthreads();
    }
    if (k == 0) g_n = red[0];
}

__global__ void ema2_kernel(const float* __restrict__ ema_w, const float* __restrict__ necs,
                            float* __restrict__ ncb)
{
    int k = blockIdx.x, d = threadIdx.x;
    float n = g_n;
    float smoothed = (necs[k] + 1e-5f) / (n + 1024.f * 1e-5f) * n;
    size_t idx = (size_t)k * ND + d;
    float nw = ema_w[idx] * 0.99f + 0.01f * g_sumcur[idx];
    ncb[idx] = nw / smoothed;
    g_sumcur[idx] = 0.f;   // self-reset
}

// ---------------- host launcher ---------------------------------------------------
extern "C" void kernel_launch(void* const* d_in, const int* in_sizes, int n_in,
                              void* d_out, int out_size)
{
    const float* X = (const float*)d_in[0];
    const float *W[6], *Bi[6], *G[5], *Be[5];

    // dict order: x, (w_i,b_i)x6, (g_i,be_i)x5, codebook, ema_w, ecs
    // sig  order: x, (w_i,b_i,g_i,be_i)x5, w6, b6, codebook, ema_w, ecs
    bool sig = (in_sizes[3] == 256);
    if (!sig) {
        for (int i = 0; i < 6; i++) { W[i] = (const float*)d_in[1 + 2 * i]; Bi[i] = (const float*)d_in[2 + 2 * i]; }
        for (int i = 0; i < 5; i++) { G[i] = (const float*)d_in[13 + 2 * i]; Be[i] = (const float*)d_in[14 + 2 * i]; }
    } else {
        for (int i = 0; i < 5; i++) {
            W[i]  = (const float*)d_in[1 + 4 * i];
            Bi[i] = (const float*)d_in[2 + 4 * i];
            G[i]  = (const float*)d_in[3 + 4 * i];
            Be[i] = (const float*)d_in[4 + 4 * i];
        }
        W[5] = (const float*)d_in[21];
        Bi[5] = (const float*)d_in[22];
    }
    const float* codebook = (const float*)d_in[23];
    const float* ema_w    = (const float*)d_in[24];
    const float* ecs      = (const float*)d_in[25];

    float* out  = (float*)d_out;
    float* ze   = out;
    float* zq   = out + (size_t)33554432;
    float* ncb  = out + (size_t)67108864;
    float* necs = out + (size_t)67371008;

    float *bufA = nullptr, *bufB = nullptr;
    cudaGetSymbolAddress((void**)&bufA, g_bufA);
    cudaGetSymbolAddress((void**)&bufB, g_bufB);

    dim3 blk(256);
    // L1: x(4096) -> A(4097), pad 2
    conv1_kernel<<<dim3(65, 4, 32), blk>>>(X, W[0], Bi[0], bufA);
    scaleshift_kernel<<<1, 256>>>(G[0], Be[0], (double)(32.0 * 4097.0));
    // L2: A(4097) -> B(4096), pad 1
    convDD_kernel<<<dim3(64, 4, 32), blk>>>(bufA, W[1], Bi[1], bufB, 4097, 4096, 1, 0, 1);
    scaleshift_kernel<<<1, 256>>>(G[1], Be[1], (double)(32.0 * 4096.0));
    // L3: B(4096) -> A(4097), pad 2
    convDD_kernel<<<dim3(65, 4, 32), blk>>>(bufB, W[2], Bi[2], bufA, 4096, 4097, 2, 0, 1);
    scaleshift_kernel<<<1, 256>>>(G[2], Be[2], (double)(32.0 * 4097.0));
    // L4: A(4097) -> B(4096), pad 1
    convDD_kernel<<<dim3(64, 4, 32), blk>>>(bufA, W[3], Bi[3], bufB, 4097, 4096, 1, 0, 1);
    scaleshift_kernel<<<1, 256>>>(G[3], Be[3], (double)(32.0 * 4096.0));
    // L5: B(4096) -> A(4097), pad 2
    convDD_kernel<<<dim3(65, 4, 32), blk>>>(bufB, W[4], Bi[4], bufA, 4096, 4097, 2, 0, 1);
    scaleshift_kernel<<<1, 256>>>(G[4], Be[4], (double)(32.0 * 4097.0));
    // L6: A(4097) -> z_e (4096), pad 1, no BN stats, [b][t][d] layout
    convDD_kernel<<<dim3(64, 4, 32), blk>>>(bufA, W[5], Bi[5], ze, 4097, 4096, 1, 1, 0);

    cnorm_kernel<<<128, 256>>>(codebook);
    vq_kernel<<<2048, 256>>>(ze, codebook, zq);
    ema1_kernel<<<1, 1024>>>(ecs, necs);
    ema2_kernel<<<1024, 256>>>(ema_w, necs, ncb);
}